// round 3
// baseline (speedup 1.0000x reference)
#include <cuda_runtime.h>
#include <math.h>

#define HID    1024
#define INP    512
#define BATCH  64
#define TT     512
#define KSPLIT 4
#define GRID   148
#define NTHR   256
#define NJOBS  (96 * KSPLIT)   // 96 column tiles (3 gates * 32 tiles of 32) * KSPLIT

// Scratch (device globals — allocation-free contract)
__device__ float g_xg[(size_t)3 * TT * BATCH * HID];   // input projections [g][t][b][h]
__device__ float g_part[KSPLIT * 3 * BATCH * HID];     // split-K partials [ks][g][b][h]
__device__ float g_h[2 * BATCH * HID];                 // ping-pong hidden state

// grid barrier state
__device__ unsigned g_count;
__device__ volatile unsigned g_phase;

// ---------------------------------------------------------------------------
__global__ void reset_kernel()
{
    int i = blockIdx.x * blockDim.x + threadIdx.x;
    if (i == 0) { g_count = 0; g_phase = 0; }
    if (i < BATCH * HID) g_h[i] = 0.0f;
}

// ---------------------------------------------------------------------------
// Input projection GEMM: C[g][m][h] = sum_i x[m][i] * W_g[h][i] + b_g[h]
// M = B*T = 32768, K = 512, N = 1024, g = blockIdx.z. 128x128x8 tile, 8x8 micro.
__global__ __launch_bounds__(256) void igemm_kernel(
    const float* __restrict__ x,
    const float* __restrict__ Wr, const float* __restrict__ Wz, const float* __restrict__ Wn,
    const float* __restrict__ br, const float* __restrict__ bz, const float* __restrict__ bn)
{
    const int g = blockIdx.z;
    const float* __restrict__ W    = (g == 0) ? Wr : ((g == 1) ? Wz : Wn);
    const float* __restrict__ bias = (g == 0) ? br : ((g == 1) ? bz : bn);

    __shared__ float As[8][132];
    __shared__ float Bs[8][132];

    const int row0 = blockIdx.y * 128;
    const int col0 = blockIdx.x * 128;
    const int tid  = threadIdx.x;
    const int ty   = tid >> 4;
    const int tx   = tid & 15;

    float acc[8][8];
#pragma unroll
    for (int i = 0; i < 8; i++)
#pragma unroll
        for (int j = 0; j < 8; j++) acc[i][j] = 0.0f;

    const int lr = tid >> 1;
    const int lk = (tid & 1) * 4;

    for (int k0 = 0; k0 < INP; k0 += 8) {
        float4 a4 = *(const float4*)&x[(size_t)(row0 + lr) * INP + k0 + lk];
        float4 b4 = *(const float4*)&W[(size_t)(col0 + lr) * INP + k0 + lk];
        As[lk + 0][lr] = a4.x; As[lk + 1][lr] = a4.y;
        As[lk + 2][lr] = a4.z; As[lk + 3][lr] = a4.w;
        Bs[lk + 0][lr] = b4.x; Bs[lk + 1][lr] = b4.y;
        Bs[lk + 2][lr] = b4.z; Bs[lk + 3][lr] = b4.w;
        __syncthreads();

#pragma unroll
        for (int kk = 0; kk < 8; kk++) {
            float4 ra0 = *(const float4*)&As[kk][ty * 8];
            float4 ra1 = *(const float4*)&As[kk][ty * 8 + 4];
            float4 rb0 = *(const float4*)&Bs[kk][tx * 8];
            float4 rb1 = *(const float4*)&Bs[kk][tx * 8 + 4];
            float ra[8] = {ra0.x, ra0.y, ra0.z, ra0.w, ra1.x, ra1.y, ra1.z, ra1.w};
            float rb[8] = {rb0.x, rb0.y, rb0.z, rb0.w, rb1.x, rb1.y, rb1.z, rb1.w};
#pragma unroll
            for (int i = 0; i < 8; i++)
#pragma unroll
                for (int j = 0; j < 8; j++) acc[i][j] += ra[i] * rb[j];
        }
        __syncthreads();
    }

#pragma unroll
    for (int i = 0; i < 8; i++) {
        const int row = row0 + ty * 8 + i;
        const int b   = row >> 9;
        const int t   = row & (TT - 1);
        const size_t base = (((size_t)g * TT + t) * BATCH + b) * HID + col0 + tx * 8;
        float v[8];
#pragma unroll
        for (int j = 0; j < 8; j++) v[j] = acc[i][j] + bias[col0 + tx * 8 + j];
        *(float4*)&g_xg[base]     = make_float4(v[0], v[1], v[2], v[3]);
        *(float4*)&g_xg[base + 4] = make_float4(v[4], v[5], v[6], v[7]);
    }
}

// ---------------------------------------------------------------------------
// Grid barrier (sense-reversing, single wave of GRID blocks)
__device__ __forceinline__ void grid_barrier(unsigned& phase)
{
    __threadfence();
    __syncthreads();
    if (threadIdx.x == 0) {
        const unsigned target = phase + 1;
        if (atomicAdd(&g_count, 1) == GRID - 1) {
            g_count = 0;
            __threadfence();
            g_phase = target;
        } else {
            while (g_phase < target) { }
            __threadfence();
        }
    }
    __syncthreads();
    phase += 1;
}

// ---------------------------------------------------------------------------
// Persistent recurrence kernel: all 512 timesteps.
// Phase A: split-K GEMM partials. 384 jobs = 96 colTiles x KSPLIT.
//   Each block hosts 4 independent 64-thread groups (named barriers);
//   group q of block b handles job q*GRID + b (if < NJOBS).
//   Job: tile 64(b) x 32(h), K-chunk 256, micro 8x4.
// Phase B: combine partials + gates + state update + output write.
__global__ __launch_bounds__(NTHR, 1) void recur_kernel(
    const float* __restrict__ Wr, const float* __restrict__ Wz, const float* __restrict__ Wn,
    const float* __restrict__ bhr, const float* __restrict__ bhz, const float* __restrict__ bhn,
    float* __restrict__ out)
{
    __shared__ float hs[4][16][64];   // per-group [k][b]
    __shared__ float ws[4][16][32];   // per-group [k][h]

    const int tid = threadIdx.x;
    const int bid = blockIdx.x;
    const int q   = tid >> 6;        // group 0..3
    const int l   = tid & 63;        // lane within group

    const int job    = q * GRID + bid;
    const bool active = (job < NJOBS);

    // job decode (valid only if active)
    const int ks = active ? (job / 96) : 0;
    const int ct = active ? (job % 96) : 0;
    const int g  = ct >> 5;
    const int h0 = (ct & 31) * 32;
    const float* __restrict__ W = (g == 0) ? Wr : ((g == 1) ? Wz : Wn);

    const int tb = l >> 3;   // 0..7
    const int th = l & 7;    // 0..7
    const int kbase = ks * (HID / KSPLIT);

    unsigned phase = 0;

    for (int t = 0; t < TT; t++) {
        // ---------------- Phase A: partial GEMM ----------------
        if (active) {
            const float* __restrict__ hprev = &g_h[(size_t)(t & 1) * BATCH * HID];

            float acc[8][4];
#pragma unroll
            for (int i = 0; i < 8; i++)
#pragma unroll
                for (int j = 0; j < 4; j++) acc[i][j] = 0.0f;

            for (int kt = 0; kt < (HID / KSPLIT) / 16; kt++) {
                const int k0 = kbase + kt * 16;
                {
                    const float4* src = (const float4*)&hprev[(size_t)l * HID + k0];
#pragma unroll
                    for (int p = 0; p < 4; p++) {
                        float4 v = src[p];
                        hs[q][p * 4 + 0][l] = v.x; hs[q][p * 4 + 1][l] = v.y;
                        hs[q][p * 4 + 2][l] = v.z; hs[q][p * 4 + 3][l] = v.w;
                    }
                }
                if (l < 32) {
                    const float4* src = (const float4*)&W[(size_t)(h0 + l) * HID + k0];
#pragma unroll
                    for (int p = 0; p < 4; p++) {
                        float4 v = src[p];
                        ws[q][p * 4 + 0][l] = v.x; ws[q][p * 4 + 1][l] = v.y;
                        ws[q][p * 4 + 2][l] = v.z; ws[q][p * 4 + 3][l] = v.w;
                    }
                }
                asm volatile("bar.sync %0, 64;" :: "r"(q + 1));

#pragma unroll
                for (int kk = 0; kk < 16; kk++) {
                    float4 a0 = *(const float4*)&hs[q][kk][tb * 8];
                    float4 a1 = *(const float4*)&hs[q][kk][tb * 8 + 4];
                    float4 w4 = *(const float4*)&ws[q][kk][th * 4];
                    float a[8] = {a0.x, a0.y, a0.z, a0.w, a1.x, a1.y, a1.z, a1.w};
                    float w[4] = {w4.x, w4.y, w4.z, w4.w};
#pragma unroll
                    for (int i = 0; i < 8; i++)
#pragma unroll
                        for (int j = 0; j < 4; j++) acc[i][j] += a[i] * w[j];
                }
                asm volatile("bar.sync %0, 64;" :: "r"(q + 1));
            }

#pragma unroll
            for (int i = 0; i < 8; i++) {
                const int b = tb * 8 + i;
                const size_t base = (((size_t)ks * 3 + g) * BATCH + b) * HID + h0 + th * 4;
                *(float4*)&g_part[base] = make_float4(acc[i][0], acc[i][1], acc[i][2], acc[i][3]);
            }
        }

        grid_barrier(phase);

        // ---------------- Phase B: combine + gates ----------------
        {
            const float* __restrict__ hp = &g_h[(size_t)(t & 1) * BATCH * HID];
            float*       __restrict__ hn = &g_h[(size_t)((t + 1) & 1) * BATCH * HID];

            for (int idx = bid * NTHR + tid; idx < BATCH * HID; idx += GRID * NTHR) {
                const int b = idx >> 10;
                const int h = idx & (HID - 1);

                float Ar = 0.0f, Az = 0.0f, An = 0.0f;
#pragma unroll
                for (int s = 0; s < KSPLIT; s++) {
                    const size_t base = (size_t)s * 3 * BATCH * HID + idx;
                    Ar += g_part[base];
                    Az += g_part[base + (size_t)BATCH * HID];
                    An += g_part[base + (size_t)2 * BATCH * HID];
                }

                const float xr = g_xg[(((size_t)0 * TT + t) * BATCH) * HID + idx];
                const float xz = g_xg[(((size_t)1 * TT + t) * BATCH) * HID + idx];
                const float xn = g_xg[(((size_t)2 * TT + t) * BATCH) * HID + idx];
                const float hv = hp[idx];

                const float r = 1.0f / (1.0f + expf(-(xr + Ar + bhr[h])));
                const float z = 1.0f / (1.0f + expf(-(xz + Az + bhz[h])));
                const float n = tanhf(xn + r * (An + bhn[h]));
                const float hnew = (1.0f - z) * n + z * hv;

                hn[idx] = hnew;
                out[((size_t)b * TT + t) * HID + h] = hnew;
            }
        }

        grid_barrier(phase);
    }
}

// ---------------------------------------------------------------------------
extern "C" void kernel_launch(void* const* d_in, const int* in_sizes, int n_in,
                              void* d_out, int out_size)
{
    const float* x     = (const float*)d_in[0];
    const float* W_i_r = (const float*)d_in[1];
    const float* b_i_r = (const float*)d_in[2];
    const float* W_h_r = (const float*)d_in[3];
    const float* b_h_r = (const float*)d_in[4];
    const float* W_i_z = (const float*)d_in[5];
    const float* b_i_z = (const float*)d_in[6];
    const float* W_h_z = (const float*)d_in[7];
    const float* b_h_z = (const float*)d_in[8];
    const float* W_i_n = (const float*)d_in[9];
    const float* b_i_n = (const float*)d_in[10];
    const float* W_h_n = (const float*)d_in[11];
    const float* b_h_n = (const float*)d_in[12];
    float* out = (float*)d_out;

    reset_kernel<<<(BATCH * HID + 255) / 256, 256>>>();

    dim3 ig(HID / 128, (BATCH * TT) / 128, 3);
    igemm_kernel<<<ig, 256>>>(x, W_i_r, W_i_z, W_i_n, b_i_r, b_i_z, b_i_n);

    recur_kernel<<<GRID, NTHR>>>(W_h_r, W_h_z, W_h_n, b_h_r, b_h_z, b_h_n, out);
}

// round 4
// speedup vs baseline: 2.0701x; 2.0701x over previous
#include <cuda_runtime.h>
#include <math.h>
#include <stdint.h>

#define HID    1024
#define INP    512
#define BATCH  64
#define TT     512
#define RGRID  128          // persistent blocks (1 per SM, <=148)
#define NTHR   256

// 48 rows of the 3072 gate-rows per block, 2 batch halves of 32
#define ROWS_PB   48
#define WS_STRIDE 1028      // 1024 + 4 pad (bank-conflict-free fragments)
#define AS_STRIDE 68        // 64 + 4 pad
#define AS_BUF    (32 * AS_STRIDE)
#define RSMEM_FLOATS (ROWS_PB * WS_STRIDE + 2 * AS_BUF)
#define RSMEM_BYTES  (RSMEM_FLOATS * 4)

// Scratch (device globals — allocation-free contract)
__device__ float g_xg[(size_t)3 * TT * BATCH * HID];   // [g][t][b][h] input projections
__device__ float g_pre[(size_t)BATCH * 3 * HID];       // [b][row] preactivations (row = g*1024+h)
__device__ float g_h[BATCH * HID];                     // hidden state (tf32-rounded)

__device__ unsigned g_count;
__device__ volatile unsigned g_phase;

// ---------------------------------------------------------------------------
__device__ __forceinline__ uint32_t f2tf(float f) {
    uint32_t u;
    asm("cvt.rna.tf32.f32 %0, %1;" : "=r"(u) : "f"(f));
    return u;
}

__device__ __forceinline__ void mma_tf32(float c[4], uint32_t a0, uint32_t a1,
                                         uint32_t a2, uint32_t a3,
                                         uint32_t b0, uint32_t b1) {
    asm volatile(
        "mma.sync.aligned.m16n8k8.row.col.f32.tf32.tf32.f32 "
        "{%0,%1,%2,%3}, {%4,%5,%6,%7}, {%8,%9}, {%0,%1,%2,%3};\n"
        : "+f"(c[0]), "+f"(c[1]), "+f"(c[2]), "+f"(c[3])
        : "r"(a0), "r"(a1), "r"(a2), "r"(a3), "r"(b0), "r"(b1));
}

__device__ __forceinline__ void cp16(float* dst_smem, const float* src) {
    uint32_t d = (uint32_t)__cvta_generic_to_shared(dst_smem);
    asm volatile("cp.async.ca.shared.global [%0], [%1], 16;\n" :: "r"(d), "l"(src));
}
__device__ __forceinline__ void cp_commit() { asm volatile("cp.async.commit_group;\n"); }
__device__ __forceinline__ void cp_wait0()  { asm volatile("cp.async.wait_group 0;\n"); }

__device__ __forceinline__ float sigmoidf_fast(float x) {
    return 1.0f / (1.0f + __expf(-x));
}
__device__ __forceinline__ float tanhf_fast(float x) {
    return 2.0f / (1.0f + __expf(-2.0f * x)) - 1.0f;
}

// ---------------------------------------------------------------------------
__global__ void reset_kernel()
{
    int i = blockIdx.x * blockDim.x + threadIdx.x;
    if (i == 0) { g_count = 0; g_phase = 0; }
    if (i < BATCH * HID) g_h[i] = 0.0f;
}

// ---------------------------------------------------------------------------
// Input projection GEMM (tf32 tensor cores):
//   g_xg[g][t][b][h] = sum_k x[b*512+t][k] * W_g[h][k] + b_g[h]
// Block tile 128m x 64n, K-chunk 16, cp.async double buffer.
// 8 warps = 4(m) x 2(n); warp tile m32 x n32 => 2 m16-tiles x 4 n8-tiles.
__global__ __launch_bounds__(256) void igemm_tf32_kernel(
    const float* __restrict__ x,
    const float* __restrict__ Wr, const float* __restrict__ Wz, const float* __restrict__ Wn,
    const float* __restrict__ br, const float* __restrict__ bz, const float* __restrict__ bn)
{
    __shared__ float xs[2][128 * 20];
    __shared__ float ws[2][64 * 20];

    const int g = blockIdx.z;
    const float* __restrict__ W    = (g == 0) ? Wr : ((g == 1) ? Wz : Wn);
    const float* __restrict__ bias = (g == 0) ? br : ((g == 1) ? bz : bn);

    const int m0 = blockIdx.y * 128;
    const int n0 = blockIdx.x * 64;
    const int tid  = threadIdx.x;
    const int w    = tid >> 5;
    const int lane = tid & 31;
    const int ar   = lane >> 2;
    const int ac   = lane & 3;
    const int wm   = w >> 1;
    const int wn   = w & 1;

    float acc[2][4][4];
#pragma unroll
    for (int mt = 0; mt < 2; mt++)
#pragma unroll
        for (int nt = 0; nt < 4; nt++)
#pragma unroll
            for (int q = 0; q < 4; q++) acc[mt][nt][q] = 0.0f;

    // chunk loader
    auto load_chunk = [&](int c) {
        const int k0 = c * 16;
        {
            int i = tid;                       // x: 512 float4
            int r = i >> 2, q = i & 3;
            cp16(&xs[c & 1][r * 20 + q * 4], &x[(size_t)(m0 + r) * INP + k0 + q * 4]);
            i = tid + 256; r = i >> 2; q = i & 3;
            cp16(&xs[c & 1][r * 20 + q * 4], &x[(size_t)(m0 + r) * INP + k0 + q * 4]);
        }
        {
            int r = tid >> 2, q = tid & 3;     // w: 256 float4
            cp16(&ws[c & 1][r * 20 + q * 4], &W[(size_t)(n0 + r) * INP + k0 + q * 4]);
        }
        cp_commit();
    };

    load_chunk(0);

    for (int c = 0; c < INP / 16; c++) {
        cp_wait0();
        __syncthreads();
        if (c + 1 < INP / 16) load_chunk(c + 1);

        const float* xb = xs[c & 1];
        const float* wb = ws[c & 1];
#pragma unroll
        for (int s = 0; s < 2; s++) {
            const int lk = s * 8;
            uint32_t afr[2][4];
#pragma unroll
            for (int mt = 0; mt < 2; mt++) {
                const int m = wm * 32 + mt * 16 + ar;
                afr[mt][0] = f2tf(xb[m * 20 + lk + ac]);
                afr[mt][1] = f2tf(xb[(m + 8) * 20 + lk + ac]);
                afr[mt][2] = f2tf(xb[m * 20 + lk + ac + 4]);
                afr[mt][3] = f2tf(xb[(m + 8) * 20 + lk + ac + 4]);
            }
#pragma unroll
            for (int nt = 0; nt < 4; nt++) {
                const int n = wn * 32 + nt * 8 + ar;
                uint32_t b0 = f2tf(wb[n * 20 + lk + ac]);
                uint32_t b1 = f2tf(wb[n * 20 + lk + ac + 4]);
#pragma unroll
                for (int mt = 0; mt < 2; mt++)
                    mma_tf32(acc[mt][nt], afr[mt][0], afr[mt][1], afr[mt][2], afr[mt][3], b0, b1);
            }
        }
        __syncthreads();
    }

    // epilogue: add bias, write g_xg[g][t][b][h]
#pragma unroll
    for (int mt = 0; mt < 2; mt++) {
#pragma unroll
        for (int nt = 0; nt < 4; nt++) {
            const int h   = n0 + wn * 32 + nt * 8 + ac * 2;
            const float bv0 = bias[h], bv1 = bias[h + 1];

            int row = m0 + wm * 32 + mt * 16 + ar;
            int b = row >> 9, t = row & (TT - 1);
            size_t base = (((size_t)g * TT + t) * BATCH + b) * HID + h;
            *(float2*)&g_xg[base] = make_float2(acc[mt][nt][0] + bv0, acc[mt][nt][1] + bv1);

            row += 8;
            b = row >> 9; t = row & (TT - 1);
            base = (((size_t)g * TT + t) * BATCH + b) * HID + h;
            *(float2*)&g_xg[base] = make_float2(acc[mt][nt][2] + bv0, acc[mt][nt][3] + bv1);
        }
    }
}

// ---------------------------------------------------------------------------
__device__ __forceinline__ void grid_barrier(unsigned& phase)
{
    __threadfence();
    __syncthreads();
    if (threadIdx.x == 0) {
        const unsigned target = phase + 1;
        if (atomicAdd(&g_count, 1) == RGRID - 1) {
            g_count = 0;
            __threadfence();
            g_phase = target;
        } else {
            while (g_phase < target) { }
            __threadfence();
        }
    }
    __syncthreads();
    phase += 1;
}

// ---------------------------------------------------------------------------
// Persistent recurrence kernel (tf32 tensor cores).
// Block b: rg = b>>1 owns gate-rows [rg*48, rg*48+48); bh = b&1 owns batches
// [bh*32, bh*32+32). W tile (48x1024, tf32-rounded) resident in smem for all
// 512 steps. Per step: stream h half via cp.async, 12 m16n8 MMA tiles,
// write preactivations, grid barrier, fused gate epilogue, grid barrier.
__global__ __launch_bounds__(NTHR, 1) void recur_kernel(
    const float* __restrict__ Wr, const float* __restrict__ Wz, const float* __restrict__ Wn,
    const float* __restrict__ bhr, const float* __restrict__ bhz, const float* __restrict__ bhn,
    float* __restrict__ out)
{
    extern __shared__ float sm[];
    float* Ws = sm;                          // [48][1028]
    float* As = sm + ROWS_PB * WS_STRIDE;    // [2][32][68]

    const int tid  = threadIdx.x;
    const int bid  = blockIdx.x;
    const int w    = tid >> 5;
    const int lane = tid & 31;
    const int ar   = lane >> 2;
    const int ac   = lane & 3;

    const int rg = bid >> 1;
    const int bh = bid & 1;
    const int R0 = rg * ROWS_PB;
    const int B0 = bh * 32;

    // ---- prologue: load + tf32-round W tile into smem ----
    for (int i = tid; i < ROWS_PB * 256; i += NTHR) {
        const int r  = i >> 8;            // 0..47
        const int q4 = i & 255;           // float4 index within row
        const int rho = R0 + r;
        const int gg  = rho >> 10;
        const int hc  = rho & (HID - 1);
        const float* __restrict__ Wg = (gg == 0) ? Wr : ((gg == 1) ? Wz : Wn);
        float4 v = *(const float4*)&Wg[(size_t)hc * HID + q4 * 4];
        float* d = &Ws[r * WS_STRIDE + q4 * 4];
        d[0] = __uint_as_float(f2tf(v.x));
        d[1] = __uint_as_float(f2tf(v.y));
        d[2] = __uint_as_float(f2tf(v.z));
        d[3] = __uint_as_float(f2tf(v.w));
    }
    __syncthreads();

    // warp tile assignment: 12 C tiles (2m x 6n); warps 0-3 get two tiles
    const bool two = (w < 4);
    const int  mi  = w & 1;
    const int  m0  = mi * 16;
    const int  n0a = (w >> 1) * 8;
    const int  n0b = n0a + 32;

    unsigned phase = 0;

    auto load_hchunk = [&](int c) {
        const int k0 = c * 64;
#pragma unroll
        for (int rep = 0; rep < 2; rep++) {
            const int i = tid + rep * 256;   // 512 float4 per chunk
            const int b = i >> 4, q = i & 15;
            cp16(&As[(c & 1) * AS_BUF + b * AS_STRIDE + q * 4],
                 &g_h[(size_t)(B0 + b) * HID + k0 + q * 4]);
        }
        cp_commit();
    };

    for (int t = 0; t < TT; t++) {
        // ---------------- Phase A: preactivation GEMM ----------------
        float acc0[4] = {0, 0, 0, 0};
        float acc1[4] = {0, 0, 0, 0};

        load_hchunk(0);
        for (int c = 0; c < HID / 64; c++) {
            cp_wait0();
            __syncthreads();
            if (c + 1 < HID / 64) load_hchunk(c + 1);

            const float* Ab = &As[(c & 1) * AS_BUF];
#pragma unroll
            for (int s = 0; s < 8; s++) {
                const int lk = s * 8;
                const float* Ap = &Ab[(m0 + ar) * AS_STRIDE + lk + ac];
                uint32_t a0 = __float_as_uint(Ap[0]);
                uint32_t a1 = __float_as_uint(Ap[8 * AS_STRIDE]);
                uint32_t a2 = __float_as_uint(Ap[4]);
                uint32_t a3 = __float_as_uint(Ap[8 * AS_STRIDE + 4]);

                const int kg = c * 64 + lk + ac;
                {
                    const float* Bp = &Ws[(n0a + ar) * WS_STRIDE + kg];
                    uint32_t b0 = __float_as_uint(Bp[0]);
                    uint32_t b1 = __float_as_uint(Bp[4]);
                    mma_tf32(acc0, a0, a1, a2, a3, b0, b1);
                }
                if (two) {
                    const float* Bp = &Ws[(n0b + ar) * WS_STRIDE + kg];
                    uint32_t b0 = __float_as_uint(Bp[0]);
                    uint32_t b1 = __float_as_uint(Bp[4]);
                    mma_tf32(acc1, a0, a1, a2, a3, b0, b1);
                }
            }
            __syncthreads();
        }

        // write preactivations g_pre[b][row]
        {
            const int bg  = B0 + m0 + ar;
            const int rho = R0 + n0a + ac * 2;
            *(float2*)&g_pre[(size_t)bg * 3072 + rho]       = make_float2(acc0[0], acc0[1]);
            *(float2*)&g_pre[(size_t)(bg + 8) * 3072 + rho] = make_float2(acc0[2], acc0[3]);
            if (two) {
                const int rho2 = R0 + n0b + ac * 2;
                *(float2*)&g_pre[(size_t)bg * 3072 + rho2]       = make_float2(acc1[0], acc1[1]);
                *(float2*)&g_pre[(size_t)(bg + 8) * 3072 + rho2] = make_float2(acc1[2], acc1[3]);
            }
        }

        grid_barrier(phase);

        // ---------------- Phase B: gates + state update ----------------
        for (int idx = bid * NTHR + tid; idx < BATCH * HID; idx += RGRID * NTHR) {
            const int b = idx >> 10;
            const int h = idx & (HID - 1);

            const float Ar = g_pre[(size_t)b * 3072 + h];
            const float Az = g_pre[(size_t)b * 3072 + 1024 + h];
            const float An = g_pre[(size_t)b * 3072 + 2048 + h];

            const float xr = g_xg[(((size_t)0 * TT + t) * BATCH) * HID + idx];
            const float xz = g_xg[(((size_t)1 * TT + t) * BATCH) * HID + idx];
            const float xn = g_xg[(((size_t)2 * TT + t) * BATCH) * HID + idx];
            const float hv = g_h[idx];

            const float r = sigmoidf_fast(xr + Ar + bhr[h]);
            const float z = sigmoidf_fast(xz + Az + bhz[h]);
            const float n = tanhf_fast(xn + r * (An + bhn[h]));
            const float hnew = (1.0f - z) * n + z * hv;

            g_h[idx] = __uint_as_float(f2tf(hnew));   // tf32-rounded state for MMA
            out[((size_t)b * TT + t) * HID + h] = hnew;
        }

        grid_barrier(phase);
    }
}

// ---------------------------------------------------------------------------
extern "C" void kernel_launch(void* const* d_in, const int* in_sizes, int n_in,
                              void* d_out, int out_size)
{
    const float* x     = (const float*)d_in[0];
    const float* W_i_r = (const float*)d_in[1];
    const float* b_i_r = (const float*)d_in[2];
    const float* W_h_r = (const float*)d_in[3];
    const float* b_h_r = (const float*)d_in[4];
    const float* W_i_z = (const float*)d_in[5];
    const float* b_i_z = (const float*)d_in[6];
    const float* W_h_z = (const float*)d_in[7];
    const float* b_h_z = (const float*)d_in[8];
    const float* W_i_n = (const float*)d_in[9];
    const float* b_i_n = (const float*)d_in[10];
    const float* W_h_n = (const float*)d_in[11];
    const float* b_h_n = (const float*)d_in[12];
    float* out = (float*)d_out;

    cudaFuncSetAttribute(recur_kernel, cudaFuncAttributeMaxDynamicSharedMemorySize,
                         RSMEM_BYTES);

    reset_kernel<<<(BATCH * HID + 255) / 256, 256>>>();

    dim3 ig(HID / 64, (BATCH * TT) / 128, 3);
    igemm_tf32_kernel<<<ig, 256>>>(x, W_i_r, W_i_z, W_i_n, b_i_r, b_i_z, b_i_n);

    recur_kernel<<<RGRID, NTHR, RSMEM_BYTES>>>(W_h_r, W_h_z, W_h_n,
                                               b_h_r, b_h_z, b_h_n, out);
}

// round 5
// speedup vs baseline: 3.4656x; 1.6742x over previous
#include <cuda_runtime.h>
#include <math.h>
#include <stdint.h>

#define HID    1024
#define INP    512
#define BATCH  64
#define TT     512
#define RGRID  128
#define NTHR   256

#define ASTR     132                       // 128 + 4 pad
#define AS_BUF   (64 * ASTR)               // one A chunk: 64 batches x 128 k
#define RED_OFF  (2 * AS_BUF)
#define PRE_OFF  (RED_OFF + 8 * 12 * 128)  // red: [8 warps][12 tiles][32 lanes][4]
#define PRE_STR  68
#define RSMEM_FLOATS (PRE_OFF + 24 * PRE_STR)
#define RSMEM_BYTES  (RSMEM_FLOATS * 4)

// Scratch (device globals — allocation-free contract)
__device__ float g_xg[(size_t)3 * TT * BATCH * HID];   // [g][t][b][h] input projections
__device__ float g_h[BATCH * HID];                     // hidden state (tf32-rounded)
__device__ unsigned g_count;                           // monotonic barrier counter

// ---------------------------------------------------------------------------
__device__ __forceinline__ uint32_t f2tf(float f) {
    uint32_t u;
    asm("cvt.rna.tf32.f32 %0, %1;" : "=r"(u) : "f"(f));
    return u;
}

__device__ __forceinline__ void mma_tf32(float c[4], uint32_t a0, uint32_t a1,
                                         uint32_t a2, uint32_t a3,
                                         uint32_t b0, uint32_t b1) {
    asm volatile(
        "mma.sync.aligned.m16n8k8.row.col.f32.tf32.tf32.f32 "
        "{%0,%1,%2,%3}, {%4,%5,%6,%7}, {%8,%9}, {%0,%1,%2,%3};\n"
        : "+f"(c[0]), "+f"(c[1]), "+f"(c[2]), "+f"(c[3])
        : "r"(a0), "r"(a1), "r"(a2), "r"(a3), "r"(b0), "r"(b1));
}

__device__ __forceinline__ void cp16ca(float* dst, const float* src) {
    uint32_t d = (uint32_t)__cvta_generic_to_shared(dst);
    asm volatile("cp.async.ca.shared.global [%0], [%1], 16;\n" :: "r"(d), "l"(src));
}
__device__ __forceinline__ void cp16cg(float* dst, const float* src) {
    uint32_t d = (uint32_t)__cvta_generic_to_shared(dst);
    asm volatile("cp.async.cg.shared.global [%0], [%1], 16;\n" :: "r"(d), "l"(src));
}
__device__ __forceinline__ void cp_commit() { asm volatile("cp.async.commit_group;\n"); }

__device__ __forceinline__ float sigmoidf_fast(float x) {
    return 1.0f / (1.0f + __expf(-x));
}
__device__ __forceinline__ float tanhf_fast(float x) {
    return 2.0f / (1.0f + __expf(-2.0f * x)) - 1.0f;
}

// ---------------------------------------------------------------------------
__global__ void reset_kernel()
{
    int i = blockIdx.x * blockDim.x + threadIdx.x;
    if (i == 0) g_count = 0u;
    if (i < BATCH * HID) g_h[i] = 0.0f;
}

// ---------------------------------------------------------------------------
// Input projection GEMM (tf32) — unchanged from round 4 (known-good).
__global__ __launch_bounds__(256) void igemm_tf32_kernel(
    const float* __restrict__ x,
    const float* __restrict__ Wr, const float* __restrict__ Wz, const float* __restrict__ Wn,
    const float* __restrict__ br, const float* __restrict__ bz, const float* __restrict__ bn)
{
    __shared__ float xs[2][128 * 20];
    __shared__ float ws[2][64 * 20];

    const int g = blockIdx.z;
    const float* __restrict__ W    = (g == 0) ? Wr : ((g == 1) ? Wz : Wn);
    const float* __restrict__ bias = (g == 0) ? br : ((g == 1) ? bz : bn);

    const int m0 = blockIdx.y * 128;
    const int n0 = blockIdx.x * 64;
    const int tid  = threadIdx.x;
    const int w    = tid >> 5;
    const int lane = tid & 31;
    const int ar   = lane >> 2;
    const int ac   = lane & 3;
    const int wm   = w >> 1;
    const int wn   = w & 1;

    float acc[2][4][4];
#pragma unroll
    for (int mt = 0; mt < 2; mt++)
#pragma unroll
        for (int nt = 0; nt < 4; nt++)
#pragma unroll
            for (int q = 0; q < 4; q++) acc[mt][nt][q] = 0.0f;

    auto load_chunk = [&](int c) {
        const int k0 = c * 16;
        {
            int i = tid;
            int r = i >> 2, q = i & 3;
            cp16ca(&xs[c & 1][r * 20 + q * 4], &x[(size_t)(m0 + r) * INP + k0 + q * 4]);
            i = tid + 256; r = i >> 2; q = i & 3;
            cp16ca(&xs[c & 1][r * 20 + q * 4], &x[(size_t)(m0 + r) * INP + k0 + q * 4]);
        }
        {
            int r = tid >> 2, q = tid & 3;
            cp16ca(&ws[c & 1][r * 20 + q * 4], &W[(size_t)(n0 + r) * INP + k0 + q * 4]);
        }
        cp_commit();
    };

    load_chunk(0);

    for (int c = 0; c < INP / 16; c++) {
        asm volatile("cp.async.wait_group 0;\n");
        __syncthreads();
        if (c + 1 < INP / 16) load_chunk(c + 1);

        const float* xb = xs[c & 1];
        const float* wb = ws[c & 1];
#pragma unroll
        for (int s = 0; s < 2; s++) {
            const int lk = s * 8;
            uint32_t afr[2][4];
#pragma unroll
            for (int mt = 0; mt < 2; mt++) {
                const int m = wm * 32 + mt * 16 + ar;
                afr[mt][0] = f2tf(xb[m * 20 + lk + ac]);
                afr[mt][1] = f2tf(xb[(m + 8) * 20 + lk + ac]);
                afr[mt][2] = f2tf(xb[m * 20 + lk + ac + 4]);
                afr[mt][3] = f2tf(xb[(m + 8) * 20 + lk + ac + 4]);
            }
#pragma unroll
            for (int nt = 0; nt < 4; nt++) {
                const int n = wn * 32 + nt * 8 + ar;
                uint32_t b0 = f2tf(wb[n * 20 + lk + ac]);
                uint32_t b1 = f2tf(wb[n * 20 + lk + ac + 4]);
#pragma unroll
                for (int mt = 0; mt < 2; mt++)
                    mma_tf32(acc[mt][nt], afr[mt][0], afr[mt][1], afr[mt][2], afr[mt][3], b0, b1);
            }
        }
        __syncthreads();
    }

#pragma unroll
    for (int mt = 0; mt < 2; mt++) {
#pragma unroll
        for (int nt = 0; nt < 4; nt++) {
            const int h   = n0 + wn * 32 + nt * 8 + ac * 2;
            const float bv0 = bias[h], bv1 = bias[h + 1];

            int row = m0 + wm * 32 + mt * 16 + ar;
            int b = row >> 9, t = row & (TT - 1);
            size_t base = (((size_t)g * TT + t) * BATCH + b) * HID + h;
            *(float2*)&g_xg[base] = make_float2(acc[mt][nt][0] + bv0, acc[mt][nt][1] + bv1);

            row += 8;
            b = row >> 9; t = row & (TT - 1);
            base = (((size_t)g * TT + t) * BATCH + b) * HID + h;
            *(float2*)&g_xg[base] = make_float2(acc[mt][nt][2] + bv0, acc[mt][nt][3] + bv1);
        }
    }
}

// ---------------------------------------------------------------------------
// Grid barrier: monotonic counter, release-add / acquire-load (no L1 flush).
__device__ __forceinline__ void grid_barrier(unsigned& phase)
{
    phase += 1;
    const unsigned target = phase * RGRID;
    __syncthreads();
    if (threadIdx.x == 0) {
        unsigned old;
        asm volatile("atom.add.release.gpu.u32 %0, [%1], 1;"
                     : "=r"(old) : "l"(&g_count) : "memory");
        unsigned v = old + 1;
        while (v < target) {
            asm volatile("ld.acquire.gpu.u32 %0, [%1];"
                         : "=r"(v) : "l"(&g_count) : "memory");
        }
    }
    __syncthreads();
}

// ---------------------------------------------------------------------------
// Persistent recurrence kernel, W-in-registers, one grid barrier per step.
// Block bid owns h-columns H0=bid*8..+8 => gate rows {H0..}, {1024+H0..},
// {2048+H0..} (24 rows). GEMM per step: D[64 b][24 rows] = h[64x1024] @ W^T.
// m = batch (4 m16 tiles), n = 24 rows (3 n8 tiles = gates), k split 8 warps.
// A staged in smem (cp.async.cg, k-chunks of 128, double buffered); B (W)
// lives in 96 regs/thread for the whole kernel. Intra-block k-reduction in
// smem, fused gate epilogue, single grid barrier.
__global__ __launch_bounds__(NTHR, 1) void recur_kernel(
    const float* __restrict__ Wr, const float* __restrict__ Wz, const float* __restrict__ Wn,
    const float* __restrict__ bhr, const float* __restrict__ bhz, const float* __restrict__ bhn,
    float* __restrict__ out)
{
    extern __shared__ float sm[];
    float* As  = sm;              // [2][64][ASTR]
    float* red = sm + RED_OFF;    // [8][12][32][4]
    float* pre = sm + PRE_OFF;    // [24][PRE_STR]

    const int tid  = threadIdx.x;
    const int bid  = blockIdx.x;
    const int w    = tid >> 5;
    const int lane = tid & 31;
    const int ar   = lane >> 2;
    const int ac   = lane & 3;
    const int H0   = bid * 8;

    // epilogue mapping: outputs (eb, ec) and (eb+32, ec)
    const int eb = tid >> 3;
    const int ec = tid & 7;
    const float bR = __ldg(&bhr[H0 + ec]);
    const float bZ = __ldg(&bhz[H0 + ec]);
    const float bN = __ldg(&bhn[H0 + ec]);

    // ---- W fragments into registers (tf32-rounded), resident for all steps ----
    uint32_t wreg[8][2][3][2];
#pragma unroll
    for (int c = 0; c < 8; c++)
#pragma unroll
        for (int s = 0; s < 2; s++) {
            const int k = c * 128 + (s * 8 + w) * 8 + ac;
#pragma unroll
            for (int nt = 0; nt < 3; nt++) {
                const float* __restrict__ Wp = (nt == 0) ? Wr : ((nt == 1) ? Wz : Wn);
                const float* q = &Wp[(size_t)(H0 + ar) * HID + k];
                wreg[c][s][nt][0] = f2tf(q[0]);
                wreg[c][s][nt][1] = f2tf(q[4]);
            }
        }

    auto load_chunk = [&](int c) {
        const int k0 = c * 128;
        float* dst = &As[(c & 1) * AS_BUF];
#pragma unroll
        for (int rep = 0; rep < 8; rep++) {
            const int idx = rep * 256 + tid;
            const int b = idx >> 5, q = idx & 31;
            cp16cg(&dst[b * ASTR + q * 4], &g_h[(size_t)b * HID + k0 + q * 4]);
        }
        cp_commit();
    };

    unsigned phase = 0;

    for (int t = 0; t < TT; t++) {
        // prefetch epilogue operands early (independent of phase A)
        const size_t xo = (size_t)t * BATCH * HID + (size_t)eb * HID + H0 + ec;
        const float xr0 = __ldg(&g_xg[xo]);
        const float xz0 = __ldg(&g_xg[(size_t)TT * BATCH * HID + xo]);
        const float xn0 = __ldg(&g_xg[(size_t)2 * TT * BATCH * HID + xo]);
        const float xr1 = __ldg(&g_xg[xo + (size_t)32 * HID]);
        const float xz1 = __ldg(&g_xg[(size_t)TT * BATCH * HID + xo + (size_t)32 * HID]);
        const float xn1 = __ldg(&g_xg[(size_t)2 * TT * BATCH * HID + xo + (size_t)32 * HID]);
        const float hv0 = g_h[(size_t)eb * HID + H0 + ec];
        const float hv1 = g_h[(size_t)(eb + 32) * HID + H0 + ec];

        // ---------------- Phase A: D = h @ W^T (k-split over warps) ----------
        float acc[4][3][4];
#pragma unroll
        for (int mt = 0; mt < 4; mt++)
#pragma unroll
            for (int nt = 0; nt < 3; nt++)
#pragma unroll
                for (int q = 0; q < 4; q++) acc[mt][nt][q] = 0.0f;

        load_chunk(0);
#pragma unroll
        for (int c = 0; c < 8; c++) {
            if (c < 7) {
                load_chunk(c + 1);
                asm volatile("cp.async.wait_group 1;\n");
            } else {
                asm volatile("cp.async.wait_group 0;\n");
            }
            __syncthreads();

            const float* Ab = &As[(c & 1) * AS_BUF];
#pragma unroll
            for (int s = 0; s < 2; s++) {
                const int kk = (s * 8 + w) * 8 + ac;
#pragma unroll
                for (int mt = 0; mt < 4; mt++) {
                    const float* Ap = &Ab[(mt * 16 + ar) * ASTR + kk];
                    const uint32_t a0 = __float_as_uint(Ap[0]);
                    const uint32_t a1 = __float_as_uint(Ap[8 * ASTR]);
                    const uint32_t a2 = __float_as_uint(Ap[4]);
                    const uint32_t a3 = __float_as_uint(Ap[8 * ASTR + 4]);
#pragma unroll
                    for (int nt = 0; nt < 3; nt++)
                        mma_tf32(acc[mt][nt], a0, a1, a2, a3,
                                 wreg[c][s][nt][0], wreg[c][s][nt][1]);
                }
            }
            __syncthreads();
        }

        // ---------------- k-reduction across the 8 warps ----------------
#pragma unroll
        for (int mt = 0; mt < 4; mt++)
#pragma unroll
            for (int nt = 0; nt < 3; nt++) {
                const int tile = mt * 3 + nt;
                *(float4*)&red[((w * 12 + tile) * 32 + lane) * 4] =
                    make_float4(acc[mt][nt][0], acc[mt][nt][1],
                                acc[mt][nt][2], acc[mt][nt][3]);
            }
        __syncthreads();

#pragma unroll
        for (int j = 0; j < 6; j++) {
            const int o    = tid + j * 256;           // 0..1535
            const int tile = o >> 7;
            const int rem  = o & 127;
            const int lo   = rem >> 2;
            const int q    = rem & 3;
            float ssum = 0.0f;
#pragma unroll
            for (int w2 = 0; w2 < 8; w2++)
                ssum += red[((w2 * 12 + tile) * 32 + lo) * 4 + q];
            const int mt = tile / 3;
            const int nt = tile - mt * 3;
            const int m  = mt * 16 + (lo >> 2) + (q >> 1) * 8;   // batch
            const int jj = nt * 8 + (lo & 3) * 2 + (q & 1);      // gate*8 + col
            pre[jj * PRE_STR + m] = ssum;
        }
        __syncthreads();

        // ---------------- fused gate epilogue (local rows) ----------------
        {
            const float pr0 = pre[ec * PRE_STR + eb];
            const float pz0 = pre[(8 + ec) * PRE_STR + eb];
            const float pn0 = pre[(16 + ec) * PRE_STR + eb];
            const float r0 = sigmoidf_fast(xr0 + pr0 + bR);
            const float z0 = sigmoidf_fast(xz0 + pz0 + bZ);
            const float n0 = tanhf_fast(xn0 + r0 * (pn0 + bN));
            const float h0 = (1.0f - z0) * n0 + z0 * hv0;
            g_h[(size_t)eb * HID + H0 + ec] = __uint_as_float(f2tf(h0));
            out[((size_t)eb * TT + t) * HID + H0 + ec] = h0;

            const float pr1 = pre[ec * PRE_STR + eb + 32];
            const float pz1 = pre[(8 + ec) * PRE_STR + eb + 32];
            const float pn1 = pre[(16 + ec) * PRE_STR + eb + 32];
            const float r1 = sigmoidf_fast(xr1 + pr1 + bR);
            const float z1 = sigmoidf_fast(xz1 + pz1 + bZ);
            const float n1 = tanhf_fast(xn1 + r1 * (pn1 + bN));
            const float h1 = (1.0f - z1) * n1 + z1 * hv1;
            g_h[(size_t)(eb + 32) * HID + H0 + ec] = __uint_as_float(f2tf(h1));
            out[((size_t)(eb + 32) * TT + t) * HID + H0 + ec] = h1;
        }

        grid_barrier(phase);
    }
}

// ---------------------------------------------------------------------------
extern "C" void kernel_launch(void* const* d_in, const int* in_sizes, int n_in,
                              void* d_out, int out_size)
{
    const float* x     = (const float*)d_in[0];
    const float* W_i_r = (const float*)d_in[1];
    const float* b_i_r = (const float*)d_in[2];
    const float* W_h_r = (const float*)d_in[3];
    const float* b_h_r = (const float*)d_in[4];
    const float* W_i_z = (const float*)d_in[5];
    const float* b_i_z = (const float*)d_in[6];
    const float* W_h_z = (const float*)d_in[7];
    const float* b_h_z = (const float*)d_in[8];
    const float* W_i_n = (const float*)d_in[9];
    const float* b_i_n = (const float*)d_in[10];
    const float* W_h_n = (const float*)d_in[11];
    const float* b_h_n = (const float*)d_in[12];
    float* out = (float*)d_out;

    cudaFuncSetAttribute(recur_kernel, cudaFuncAttributeMaxDynamicSharedMemorySize,
                         RSMEM_BYTES);

    reset_kernel<<<(BATCH * HID + 255) / 256, 256>>>();

    dim3 ig(HID / 64, (BATCH * TT) / 128, 3);
    igemm_tf32_kernel<<<ig, 256>>>(x, W_i_r, W_i_z, W_i_n, b_i_r, b_i_z, b_i_n);

    recur_kernel<<<RGRID, NTHR, RSMEM_BYTES>>>(W_h_r, W_h_z, W_h_n,
                                               b_h_r, b_h_z, b_h_n, out);
}

// round 7
// speedup vs baseline: 3.5485x; 1.0239x over previous
#include <cuda_runtime.h>
#include <math.h>
#include <stdint.h>

#define HID    1024
#define INP    512
#define BATCH  64
#define TT     512
#define RGRID  128
#define NTHR   256

#define ASTR     132                        // 128 + 4 pad
#define AS_BUF   (64 * ASTR)                // one A chunk: 64 batches x 128 k
#define RED_OFF  (2 * AS_BUF)
#define RED_SIZE (8 * 12 * 128)             // [8 warps][12 tiles][128]
#define PRE_OFF  (RED_OFF + RED_SIZE)
#define PRE_STR  68
#define RSMEM_FLOATS (PRE_OFF + 48 * PRE_STR)
#define RSMEM_BYTES  (RSMEM_FLOATS * 4)

// Scratch (device globals — allocation-free contract)
__device__ float g_xg[(size_t)3 * TT * BATCH * HID];   // [g][t][b][h] input projections
__device__ float g_h[BATCH * HID];                     // hidden state (tf32-rounded)
__device__ float g_part[128 * 1536];                   // pair-exchange partials
__device__ unsigned g_pflag[64];                       // per-pair monotonic flags
__device__ unsigned g_count;                           // global barrier counter

// ---------------------------------------------------------------------------
__device__ __forceinline__ uint32_t f2tf(float f) {
    uint32_t u;
    asm("cvt.rna.tf32.f32 %0, %1;" : "=r"(u) : "f"(f));
    return u;
}

__device__ __forceinline__ void mma_tf32(float c[4], uint32_t a0, uint32_t a1,
                                         uint32_t a2, uint32_t a3,
                                         uint32_t b0, uint32_t b1) {
    asm volatile(
        "mma.sync.aligned.m16n8k8.row.col.f32.tf32.tf32.f32 "
        "{%0,%1,%2,%3}, {%4,%5,%6,%7}, {%8,%9}, {%0,%1,%2,%3};\n"
        : "+f"(c[0]), "+f"(c[1]), "+f"(c[2]), "+f"(c[3])
        : "r"(a0), "r"(a1), "r"(a2), "r"(a3), "r"(b0), "r"(b1));
}

__device__ __forceinline__ void cp16ca(float* dst, const float* src) {
    uint32_t d = (uint32_t)__cvta_generic_to_shared(dst);
    asm volatile("cp.async.ca.shared.global [%0], [%1], 16;\n" :: "r"(d), "l"(src));
}
__device__ __forceinline__ void cp16cg(float* dst, const float* src) {
    uint32_t d = (uint32_t)__cvta_generic_to_shared(dst);
    asm volatile("cp.async.cg.shared.global [%0], [%1], 16;\n" :: "r"(d), "l"(src));
}
__device__ __forceinline__ void cp_commit() { asm volatile("cp.async.commit_group;\n"); }

__device__ __forceinline__ float sigmoidf_fast(float x) {
    return 1.0f / (1.0f + __expf(-x));
}
__device__ __forceinline__ float tanhf_fast(float x) {
    return 2.0f / (1.0f + __expf(-2.0f * x)) - 1.0f;
}

// L2-only global load/store (bypass non-coherent L1) — for cross-SM data.
__device__ __forceinline__ float ld_cg(const float* p) {
    float v;
    asm volatile("ld.global.cg.f32 %0, [%1];" : "=f"(v) : "l"(p));
    return v;
}
__device__ __forceinline__ void st_cg(float* p, float v) {
    asm volatile("st.global.cg.f32 [%0], %1;" :: "l"(p), "f"(v));
}

// ---------------------------------------------------------------------------
__global__ void reset_kernel()
{
    int i = blockIdx.x * blockDim.x + threadIdx.x;
    if (i == 0) g_count = 0u;
    if (i < 64) g_pflag[i] = 0u;
    if (i < BATCH * HID) g_h[i] = 0.0f;
}

// ---------------------------------------------------------------------------
// Input projection GEMM (tf32) — unchanged (known-good).
__global__ __launch_bounds__(256) void igemm_tf32_kernel(
    const float* __restrict__ x,
    const float* __restrict__ Wr, const float* __restrict__ Wz, const float* __restrict__ Wn,
    const float* __restrict__ br, const float* __restrict__ bz, const float* __restrict__ bn)
{
    __shared__ float xs[2][128 * 20];
    __shared__ float ws[2][64 * 20];

    const int g = blockIdx.z;
    const float* __restrict__ W    = (g == 0) ? Wr : ((g == 1) ? Wz : Wn);
    const float* __restrict__ bias = (g == 0) ? br : ((g == 1) ? bz : bn);

    const int m0 = blockIdx.y * 128;
    const int n0 = blockIdx.x * 64;
    const int tid  = threadIdx.x;
    const int w    = tid >> 5;
    const int lane = tid & 31;
    const int ar   = lane >> 2;
    const int ac   = lane & 3;
    const int wm   = w >> 1;
    const int wn   = w & 1;

    float acc[2][4][4];
#pragma unroll
    for (int mt = 0; mt < 2; mt++)
#pragma unroll
        for (int nt = 0; nt < 4; nt++)
#pragma unroll
            for (int q = 0; q < 4; q++) acc[mt][nt][q] = 0.0f;

    auto load_chunk = [&](int c) {
        const int k0 = c * 16;
        {
            int i = tid;
            int r = i >> 2, q = i & 3;
            cp16ca(&xs[c & 1][r * 20 + q * 4], &x[(size_t)(m0 + r) * INP + k0 + q * 4]);
            i = tid + 256; r = i >> 2; q = i & 3;
            cp16ca(&xs[c & 1][r * 20 + q * 4], &x[(size_t)(m0 + r) * INP + k0 + q * 4]);
        }
        {
            int r = tid >> 2, q = tid & 3;
            cp16ca(&ws[c & 1][r * 20 + q * 4], &W[(size_t)(n0 + r) * INP + k0 + q * 4]);
        }
        cp_commit();
    };

    load_chunk(0);

    for (int c = 0; c < INP / 16; c++) {
        asm volatile("cp.async.wait_group 0;\n");
        __syncthreads();
        if (c + 1 < INP / 16) load_chunk(c + 1);

        const float* xb = xs[c & 1];
        const float* wb = ws[c & 1];
#pragma unroll
        for (int s = 0; s < 2; s++) {
            const int lk = s * 8;
            uint32_t afr[2][4];
#pragma unroll
            for (int mt = 0; mt < 2; mt++) {
                const int m = wm * 32 + mt * 16 + ar;
                afr[mt][0] = f2tf(xb[m * 20 + lk + ac]);
                afr[mt][1] = f2tf(xb[(m + 8) * 20 + lk + ac]);
                afr[mt][2] = f2tf(xb[m * 20 + lk + ac + 4]);
                afr[mt][3] = f2tf(xb[(m + 8) * 20 + lk + ac + 4]);
            }
#pragma unroll
            for (int nt = 0; nt < 4; nt++) {
                const int n = wn * 32 + nt * 8 + ar;
                uint32_t b0 = f2tf(wb[n * 20 + lk + ac]);
                uint32_t b1 = f2tf(wb[n * 20 + lk + ac + 4]);
#pragma unroll
                for (int mt = 0; mt < 2; mt++)
                    mma_tf32(acc[mt][nt], afr[mt][0], afr[mt][1], afr[mt][2], afr[mt][3], b0, b1);
            }
        }
        __syncthreads();
    }

#pragma unroll
    for (int mt = 0; mt < 2; mt++) {
#pragma unroll
        for (int nt = 0; nt < 4; nt++) {
            const int h   = n0 + wn * 32 + nt * 8 + ac * 2;
            const float bv0 = bias[h], bv1 = bias[h + 1];

            int row = m0 + wm * 32 + mt * 16 + ar;
            int b = row >> 9, t = row & (TT - 1);
            size_t base = (((size_t)g * TT + t) * BATCH + b) * HID + h;
            *(float2*)&g_xg[base] = make_float2(acc[mt][nt][0] + bv0, acc[mt][nt][1] + bv1);

            row += 8;
            b = row >> 9; t = row & (TT - 1);
            base = (((size_t)g * TT + t) * BATCH + b) * HID + h;
            *(float2*)&g_xg[base] = make_float2(acc[mt][nt][2] + bv0, acc[mt][nt][3] + bv1);
        }
    }
}

// ---------------------------------------------------------------------------
__device__ __forceinline__ void grid_barrier(unsigned& phase)
{
    phase += 1;
    const unsigned target = phase * RGRID;
    __syncthreads();
    if (threadIdx.x == 0) {
        unsigned old;
        asm volatile("atom.add.release.gpu.u32 %0, [%1], 1;"
                     : "=r"(old) : "l"(&g_count) : "memory");
        unsigned v = old + 1;
        while (v < target) {
            asm volatile("ld.acquire.gpu.u32 %0, [%1];"
                         : "=r"(v) : "l"(&g_count) : "memory");
        }
    }
    __syncthreads();
}

// ---------------------------------------------------------------------------
// Persistent recurrence kernel.
// 128 blocks = 64 column groups x 2 k-halves. Group gq owns h-cols
// [gq*16, gq*16+16) => 48 gate rows (layout j = gate*16 + col). Block handles
// K = [ks*512, ks*512+512). Warps: 2(n-halves) x 4(k-quarters); W fragments
// (96 regs) resident all steps; acc = 48 regs. Intra-block k-reduction in
// smem, pair exchange via gmem (L2-only ld/st!) + pair flag, epilogue split
// by batch halves, one global barrier per step.
__global__ __launch_bounds__(NTHR, 1) void recur_kernel(
    const float* __restrict__ Wr, const float* __restrict__ Wz, const float* __restrict__ Wn,
    const float* __restrict__ bhr, const float* __restrict__ bhz, const float* __restrict__ bhn,
    float* __restrict__ out)
{
    extern __shared__ float sm[];
    float* As  = sm;              // [2][64][ASTR]
    float* red = sm + RED_OFF;    // [8][12][128]
    float* pre = sm + PRE_OFF;    // [48][PRE_STR]

    const int tid  = threadIdx.x;
    const int bid  = blockIdx.x;
    const int w    = tid >> 5;
    const int lane = tid & 31;
    const int ar   = lane >> 2;
    const int ac   = lane & 3;

    const int gq  = bid >> 1;        // column group
    const int ks  = bid & 1;         // k-half
    const int H0  = gq * 16;         // h-col base
    const int KB0 = ks * 512;        // k base
    const int Bme = ks * 32;         // my epilogue batches
    const int Bpr = (ks ^ 1) * 32;   // partner's epilogue batches

    const int nh = w >> 2;           // n-half (0..1)
    const int kq = w & 3;            // k-quarter (0..3)

    // epilogue mapping: col ec, batches Bme+m0 and Bme+m0+16
    const int ec = tid & 15;
    const int m0 = tid >> 4;
    const int hcol = H0 + ec;
    const float bR = __ldg(&bhr[hcol]);
    const float bZ = __ldg(&bhz[hcol]);
    const float bN = __ldg(&bhn[hcol]);

    // ---- W fragments into registers (tf32-rounded), resident all steps ----
    uint32_t wreg[4][4][3][2];
#pragma unroll
    for (int c = 0; c < 4; c++)
#pragma unroll
        for (int s = 0; s < 4; s++) {
            const int k = KB0 + c * 128 + kq * 32 + s * 8 + ac;
#pragma unroll
            for (int nt = 0; nt < 3; nt++) {
                const int j    = nh * 24 + nt * 8 + ar;   // block-local row
                const int gate = j >> 4;
                const int col  = j & 15;
                const float* __restrict__ Wp = (gate == 0) ? Wr : ((gate == 1) ? Wz : Wn);
                const float* q = &Wp[(size_t)(H0 + col) * HID + k];
                wreg[c][s][nt][0] = f2tf(q[0]);
                wreg[c][s][nt][1] = f2tf(q[4]);
            }
        }

    auto load_chunk = [&](int c) {
        const int k0 = KB0 + c * 128;
        float* dst = &As[(c & 1) * AS_BUF];
#pragma unroll
        for (int rep = 0; rep < 8; rep++) {
            const int idx = rep * 256 + tid;
            const int b = idx >> 5, q = idx & 31;
            cp16cg(&dst[b * ASTR + q * 4], &g_h[(size_t)b * HID + k0 + q * 4]);
        }
        cp_commit();
    };

    unsigned phase = 0;

    for (int t = 0; t < TT; t++) {
        // prefetch epilogue operands (g_xg static; g_h own-written last step)
        const size_t SL = (size_t)TT * BATCH * HID;
        const size_t xo0 = (size_t)t * BATCH * HID + (size_t)(Bme + m0) * HID + hcol;
        const size_t xo1 = xo0 + (size_t)16 * HID;
        const float xr0 = __ldg(&g_xg[xo0]);
        const float xz0 = __ldg(&g_xg[SL + xo0]);
        const float xn0 = __ldg(&g_xg[2 * SL + xo0]);
        const float xr1 = __ldg(&g_xg[xo1]);
        const float xz1 = __ldg(&g_xg[SL + xo1]);
        const float xn1 = __ldg(&g_xg[2 * SL + xo1]);
        const float hv0 = g_h[(size_t)(Bme + m0) * HID + hcol];
        const float hv1 = g_h[(size_t)(Bme + m0 + 16) * HID + hcol];

        // ---------------- Phase A: partial GEMM (my k-half) ----------------
        float acc[4][3][4];
#pragma unroll
        for (int mt = 0; mt < 4; mt++)
#pragma unroll
            for (int nt = 0; nt < 3; nt++)
#pragma unroll
                for (int q = 0; q < 4; q++) acc[mt][nt][q] = 0.0f;

        load_chunk(0);
#pragma unroll
        for (int c = 0; c < 4; c++) {
            if (c < 3) {
                load_chunk(c + 1);
                asm volatile("cp.async.wait_group 1;\n");
            } else {
                asm volatile("cp.async.wait_group 0;\n");
            }
            __syncthreads();

            const float* Ab = &As[(c & 1) * AS_BUF];
#pragma unroll
            for (int s = 0; s < 4; s++) {
                const int kk = kq * 32 + s * 8 + ac;
#pragma unroll
                for (int mt = 0; mt < 4; mt++) {
                    const float* Ap = &Ab[(mt * 16 + ar) * ASTR + kk];
                    const uint32_t a0 = __float_as_uint(Ap[0]);
                    const uint32_t a1 = __float_as_uint(Ap[8 * ASTR]);
                    const uint32_t a2 = __float_as_uint(Ap[4]);
                    const uint32_t a3 = __float_as_uint(Ap[8 * ASTR + 4]);
#pragma unroll
                    for (int nt = 0; nt < 3; nt++)
                        mma_tf32(acc[mt][nt], a0, a1, a2, a3,
                                 wreg[c][s][nt][0], wreg[c][s][nt][1]);
                }
            }
            __syncthreads();
        }

        // ---------------- intra-block k-reduction (4 kq warps per nh) -------
#pragma unroll
        for (int mt = 0; mt < 4; mt++)
#pragma unroll
            for (int nt = 0; nt < 3; nt++) {
                const int tile = mt * 3 + nt;
                *(float4*)&red[((w * 12 + tile) * 128) + lane * 4] =
                    make_float4(acc[mt][nt][0], acc[mt][nt][1],
                                acc[mt][nt][2], acc[mt][nt][3]);
            }
        __syncthreads();

#pragma unroll
        for (int j = 0; j < 12; j++) {
            const int nh2 = (j >= 6);
            const int o   = tid + j * 256 - nh2 * 1536;   // 0..1535 within half
            const int tile = o >> 7;
            const int rem  = o & 127;
            float ssum = 0.0f;
#pragma unroll
            for (int k2 = 0; k2 < 4; k2++)
                ssum += red[(((nh2 * 4 + k2) * 12 + tile) * 128) + rem];
            const int mt = tile / 3;
            const int nt = tile - mt * 3;
            const int la = rem >> 2;
            const int qq = rem & 3;
            const int m  = mt * 16 + (la >> 2) + (qq >> 1) * 8;          // batch
            const int n  = nh2 * 24 + nt * 8 + (la & 3) * 2 + (qq & 1);  // row
            pre[n * PRE_STR + m] = ssum;
        }
        __syncthreads();

        // ------- pair exchange: write partner-batch partials (L2-only) ------
        {
            float* dst = &g_part[(size_t)bid * 1536];
#pragma unroll
            for (int j = 0; j < 6; j++) {
                const int o = tid + j * 256;      // 0..1535
                const int n = o >> 5, m = o & 31;
                st_cg(&dst[o], pre[n * PRE_STR + Bpr + m]);
            }
        }

        // pair flag sync (release my writes, acquire partner's)
        __syncthreads();
        if (tid == 0) {
            unsigned old;
            asm volatile("atom.add.release.gpu.u32 %0, [%1], 1;"
                         : "=r"(old) : "l"(&g_pflag[gq]) : "memory");
            const unsigned target = 2u * (unsigned)(t + 1);
            unsigned v = old + 1;
            while (v < target) {
                asm volatile("ld.acquire.gpu.u32 %0, [%1];"
                             : "=r"(v) : "l"(&g_pflag[gq]) : "memory");
            }
        }
        __syncthreads();

        // -------- epilogue (my batch half, my 16 cols; L2-only pp reads) ----
        {
            const float* pp = &g_part[(size_t)(bid ^ 1) * 1536];

            const float Ar0 = pre[ec * PRE_STR + Bme + m0]        + ld_cg(&pp[ec * 32 + m0]);
            const float Az0 = pre[(16 + ec) * PRE_STR + Bme + m0] + ld_cg(&pp[(16 + ec) * 32 + m0]);
            const float An0 = pre[(32 + ec) * PRE_STR + Bme + m0] + ld_cg(&pp[(32 + ec) * 32 + m0]);
            const float r0 = sigmoidf_fast(xr0 + Ar0 + bR);
            const float z0 = sigmoidf_fast(xz0 + Az0 + bZ);
            const float n0 = tanhf_fast(xn0 + r0 * (An0 + bN));
            const float h0 = (1.0f - z0) * n0 + z0 * hv0;
            g_h[(size_t)(Bme + m0) * HID + hcol] = __uint_as_float(f2tf(h0));
            out[((size_t)(Bme + m0) * TT + t) * HID + hcol] = h0;

            const int m1 = m0 + 16;
            const float Ar1 = pre[ec * PRE_STR + Bme + m1]        + ld_cg(&pp[ec * 32 + m1]);
            const float Az1 = pre[(16 + ec) * PRE_STR + Bme + m1] + ld_cg(&pp[(16 + ec) * 32 + m1]);
            const float An1 = pre[(32 + ec) * PRE_STR + Bme + m1] + ld_cg(&pp[(32 + ec) * 32 + m1]);
            const float r1 = sigmoidf_fast(xr1 + Ar1 + bR);
            const float z1 = sigmoidf_fast(xz1 + Az1 + bZ);
            const float n1 = tanhf_fast(xn1 + r1 * (An1 + bN));
            const float h1 = (1.0f - z1) * n1 + z1 * hv1;
            g_h[(size_t)(Bme + m1) * HID + hcol] = __uint_as_float(f2tf(h1));
            out[((size_t)(Bme + m1) * TT + t) * HID + hcol] = h1;
        }

        grid_barrier(phase);
    }
}

// ---------------------------------------------------------------------------
extern "C" void kernel_launch(void* const* d_in, const int* in_sizes, int n_in,
                              void* d_out, int out_size)
{
    const float* x     = (const float*)d_in[0];
    const float* W_i_r = (const float*)d_in[1];
    const float* b_i_r = (const float*)d_in[2];
    const float* W_h_r = (const float*)d_in[3];
    const float* b_h_r = (const float*)d_in[4];
    const float* W_i_z = (const float*)d_in[5];
    const float* b_i_z = (const float*)d_in[6];
    const float* W_h_z = (const float*)d_in[7];
    const float* b_h_z = (const float*)d_in[8];
    const float* W_i_n = (const float*)d_in[9];
    const float* b_i_n = (const float*)d_in[10];
    const float* W_h_n = (const float*)d_in[11];
    const float* b_h_n = (const float*)d_in[12];
    float* out = (float*)d_out;

    cudaFuncSetAttribute(recur_kernel, cudaFuncAttributeMaxDynamicSharedMemorySize,
                         RSMEM_BYTES);

    reset_kernel<<<(BATCH * HID + 255) / 256, 256>>>();

    dim3 ig(HID / 64, (BATCH * TT) / 128, 3);
    igemm_tf32_kernel<<<ig, 256>>>(x, W_i_r, W_i_z, W_i_n, b_i_r, b_i_z, b_i_n);

    recur_kernel<<<RGRID, NTHR, RSMEM_BYTES>>>(W_h_r, W_h_z, W_h_n,
                                               b_h_r, b_h_z, b_h_n, out);
}

// round 8
// speedup vs baseline: 4.3650x; 1.2301x over previous
#include <cuda_runtime.h>
#include <cuda_fp16.h>
#include <math.h>
#include <stdint.h>

#define HID    1024
#define INP    512
#define BATCH  64
#define TT     512
#define RGRID  128
#define NTHR   256

// recurrence smem layout (bytes)
#define ASTRH     264                      // halves per A row (256 + 8 pad)
#define ABUF_B    (64 * ASTRH * 2)         // one A chunk buffer: 33792 B
#define RED_B     (8 * 12 * 128 * 4)       // 49152 B
#define PRE_STR   68
#define PRE_B     (24 * PRE_STR * 4)
#define RSMEM_BYTES (2 * ABUF_B + RED_B + PRE_B)

// Scratch (device globals — allocation-free contract)
__device__ float  g_xg[(size_t)3 * TT * BATCH * HID];  // [g][t][b][h] input projections
__device__ __half g_h[BATCH * HID];                    // hidden state (fp16)
__device__ unsigned g_count;                           // global barrier counter

// ---------------------------------------------------------------------------
__device__ __forceinline__ uint32_t f2tf(float f) {
    uint32_t u;
    asm("cvt.rna.tf32.f32 %0, %1;" : "=r"(u) : "f"(f));
    return u;
}

__device__ __forceinline__ void mma_tf32(float c[4], uint32_t a0, uint32_t a1,
                                         uint32_t a2, uint32_t a3,
                                         uint32_t b0, uint32_t b1) {
    asm volatile(
        "mma.sync.aligned.m16n8k8.row.col.f32.tf32.tf32.f32 "
        "{%0,%1,%2,%3}, {%4,%5,%6,%7}, {%8,%9}, {%0,%1,%2,%3};\n"
        : "+f"(c[0]), "+f"(c[1]), "+f"(c[2]), "+f"(c[3])
        : "r"(a0), "r"(a1), "r"(a2), "r"(a3), "r"(b0), "r"(b1));
}

__device__ __forceinline__ void mma_f16(float c[4], uint32_t a0, uint32_t a1,
                                        uint32_t a2, uint32_t a3,
                                        uint32_t b0, uint32_t b1) {
    asm volatile(
        "mma.sync.aligned.m16n8k16.row.col.f32.f16.f16.f32 "
        "{%0,%1,%2,%3}, {%4,%5,%6,%7}, {%8,%9}, {%0,%1,%2,%3};\n"
        : "+f"(c[0]), "+f"(c[1]), "+f"(c[2]), "+f"(c[3])
        : "r"(a0), "r"(a1), "r"(a2), "r"(a3), "r"(b0), "r"(b1));
}

__device__ __forceinline__ void ldsm_x4(uint32_t& r0, uint32_t& r1,
                                        uint32_t& r2, uint32_t& r3, uint32_t addr) {
    asm volatile("ldmatrix.sync.aligned.m8n8.x4.shared.b16 {%0,%1,%2,%3}, [%4];"
                 : "=r"(r0), "=r"(r1), "=r"(r2), "=r"(r3) : "r"(addr));
}

__device__ __forceinline__ void cp16ca(void* dst, const void* src) {
    uint32_t d = (uint32_t)__cvta_generic_to_shared(dst);
    asm volatile("cp.async.ca.shared.global [%0], [%1], 16;\n" :: "r"(d), "l"(src));
}
__device__ __forceinline__ void cp16cg(void* dst, const void* src) {
    uint32_t d = (uint32_t)__cvta_generic_to_shared(dst);
    asm volatile("cp.async.cg.shared.global [%0], [%1], 16;\n" :: "r"(d), "l"(src));
}
__device__ __forceinline__ void cp_commit() { asm volatile("cp.async.commit_group;\n"); }

__device__ __forceinline__ float sigmoidf_fast(float x) {
    return 1.0f / (1.0f + __expf(-x));
}
__device__ __forceinline__ float tanhf_fast(float x) {
    return 2.0f / (1.0f + __expf(-2.0f * x)) - 1.0f;
}

// ---------------------------------------------------------------------------
__global__ void reset_kernel()
{
    int i = blockIdx.x * blockDim.x + threadIdx.x;
    if (i == 0) g_count = 0u;
    if (i < BATCH * HID) g_h[i] = __float2half(0.0f);
}

// ---------------------------------------------------------------------------
// Input projection GEMM (tf32) — unchanged (known-good).
__global__ __launch_bounds__(256) void igemm_tf32_kernel(
    const float* __restrict__ x,
    const float* __restrict__ Wr, const float* __restrict__ Wz, const float* __restrict__ Wn,
    const float* __restrict__ br, const float* __restrict__ bz, const float* __restrict__ bn)
{
    __shared__ float xs[2][128 * 20];
    __shared__ float ws[2][64 * 20];

    const int g = blockIdx.z;
    const float* __restrict__ W    = (g == 0) ? Wr : ((g == 1) ? Wz : Wn);
    const float* __restrict__ bias = (g == 0) ? br : ((g == 1) ? bz : bn);

    const int m0 = blockIdx.y * 128;
    const int n0 = blockIdx.x * 64;
    const int tid  = threadIdx.x;
    const int w    = tid >> 5;
    const int lane = tid & 31;
    const int ar   = lane >> 2;
    const int ac   = lane & 3;
    const int wm   = w >> 1;
    const int wn   = w & 1;

    float acc[2][4][4];
#pragma unroll
    for (int mt = 0; mt < 2; mt++)
#pragma unroll
        for (int nt = 0; nt < 4; nt++)
#pragma unroll
            for (int q = 0; q < 4; q++) acc[mt][nt][q] = 0.0f;

    auto load_chunk = [&](int c) {
        const int k0 = c * 16;
        {
            int i = tid;
            int r = i >> 2, q = i & 3;
            cp16ca(&xs[c & 1][r * 20 + q * 4], &x[(size_t)(m0 + r) * INP + k0 + q * 4]);
            i = tid + 256; r = i >> 2; q = i & 3;
            cp16ca(&xs[c & 1][r * 20 + q * 4], &x[(size_t)(m0 + r) * INP + k0 + q * 4]);
        }
        {
            int r = tid >> 2, q = tid & 3;
            cp16ca(&ws[c & 1][r * 20 + q * 4], &W[(size_t)(n0 + r) * INP + k0 + q * 4]);
        }
        cp_commit();
    };

    load_chunk(0);

    for (int c = 0; c < INP / 16; c++) {
        asm volatile("cp.async.wait_group 0;\n");
        __syncthreads();
        if (c + 1 < INP / 16) load_chunk(c + 1);

        const float* xb = xs[c & 1];
        const float* wb = ws[c & 1];
#pragma unroll
        for (int s = 0; s < 2; s++) {
            const int lk = s * 8;
            uint32_t afr[2][4];
#pragma unroll
            for (int mt = 0; mt < 2; mt++) {
                const int m = wm * 32 + mt * 16 + ar;
                afr[mt][0] = f2tf(xb[m * 20 + lk + ac]);
                afr[mt][1] = f2tf(xb[(m + 8) * 20 + lk + ac]);
                afr[mt][2] = f2tf(xb[m * 20 + lk + ac + 4]);
                afr[mt][3] = f2tf(xb[(m + 8) * 20 + lk + ac + 4]);
            }
#pragma unroll
            for (int nt = 0; nt < 4; nt++) {
                const int n = wn * 32 + nt * 8 + ar;
                uint32_t b0 = f2tf(wb[n * 20 + lk + ac]);
                uint32_t b1 = f2tf(wb[n * 20 + lk + ac + 4]);
#pragma unroll
                for (int mt = 0; mt < 2; mt++)
                    mma_tf32(acc[mt][nt], afr[mt][0], afr[mt][1], afr[mt][2], afr[mt][3], b0, b1);
            }
        }
        __syncthreads();
    }

#pragma unroll
    for (int mt = 0; mt < 2; mt++) {
#pragma unroll
        for (int nt = 0; nt < 4; nt++) {
            const int h   = n0 + wn * 32 + nt * 8 + ac * 2;
            const float bv0 = bias[h], bv1 = bias[h + 1];

            int row = m0 + wm * 32 + mt * 16 + ar;
            int b = row >> 9, t = row & (TT - 1);
            size_t base = (((size_t)g * TT + t) * BATCH + b) * HID + h;
            *(float2*)&g_xg[base] = make_float2(acc[mt][nt][0] + bv0, acc[mt][nt][1] + bv1);

            row += 8;
            b = row >> 9; t = row & (TT - 1);
            base = (((size_t)g * TT + t) * BATCH + b) * HID + h;
            *(float2*)&g_xg[base] = make_float2(acc[mt][nt][2] + bv0, acc[mt][nt][3] + bv1);
        }
    }
}

// ---------------------------------------------------------------------------
__device__ __forceinline__ void grid_barrier(unsigned& phase)
{
    phase += 1;
    const unsigned target = phase * RGRID;
    __syncthreads();
    if (threadIdx.x == 0) {
        unsigned old;
        asm volatile("atom.add.release.gpu.u32 %0, [%1], 1;"
                     : "=r"(old) : "l"(&g_count) : "memory");
        unsigned v = old + 1;
        while (v < target) {
            asm volatile("ld.acquire.gpu.u32 %0, [%1];"
                         : "=r"(v) : "l"(&g_count) : "memory");
        }
    }
    __syncthreads();
}

// ---------------------------------------------------------------------------
// Persistent recurrence kernel, fp16 MMA (m16n8k16) + ldmatrix.
// Block bid exclusively owns h-cols [bid*8, bid*8+8) -> 24 gate rows
// (n = gate*8 + col), full K=1024. W in 48 regs/thread (fp16 pairs),
// resident for all steps. Per step: stream h (fp16) in 4 k256 chunks via
// cp.async.cg (double buffered), 24 fp16 MMAs/warp/chunk fed by ldmatrix.x4,
// 8-warp k-reduction in smem, fused gate epilogue, ONE grid barrier.
__global__ __launch_bounds__(NTHR, 1) void recur_kernel(
    const float* __restrict__ Wr, const float* __restrict__ Wz, const float* __restrict__ Wn,
    const float* __restrict__ bhr, const float* __restrict__ bhz, const float* __restrict__ bhn,
    float* __restrict__ out)
{
    extern __shared__ char smc[];
    __half* As  = (__half*)smc;                       // [2][64][ASTRH]
    float*  red = (float*)(smc + 2 * ABUF_B);         // [8][12][128]
    float*  pre = (float*)(smc + 2 * ABUF_B + RED_B); // [24][PRE_STR]

    const int tid  = threadIdx.x;
    const int bid  = blockIdx.x;
    const int w    = tid >> 5;
    const int lane = tid & 31;
    const int ar   = lane >> 2;
    const int ac   = lane & 3;
    const int H0   = bid * 8;

    // epilogue mapping: col ec (0..7), batches m0 and m0+32
    const int ec = tid & 7;
    const int m0 = tid >> 3;
    const int hcol = H0 + ec;
    const float bR = __ldg(&bhr[hcol]);
    const float bZ = __ldg(&bhz[hcol]);
    const float bN = __ldg(&bhn[hcol]);

    // ---- W fragments into registers (fp16 pairs), resident all steps ----
    // wreg[c][s2][nt][q]: chunk c (k256), k16-slice s2 within warp's k32,
    // gate nt, B-frag reg q. k = c*256 + w*32 + s2*16 + q*8 + 2*ac.
    uint32_t wreg[4][2][3][2];
#pragma unroll
    for (int c = 0; c < 4; c++)
#pragma unroll
        for (int s2 = 0; s2 < 2; s2++)
#pragma unroll
            for (int nt = 0; nt < 3; nt++) {
                const float* __restrict__ Wp = (nt == 0) ? Wr : ((nt == 1) ? Wz : Wn);
                const float* rowp = &Wp[(size_t)(H0 + ar) * HID];
#pragma unroll
                for (int q = 0; q < 2; q++) {
                    const int k = c * 256 + w * 32 + s2 * 16 + q * 8 + 2 * ac;
                    float2 v = *(const float2*)&rowp[k];
                    __half2 h2 = __floats2half2_rn(v.x, v.y);
                    wreg[c][s2][nt][q] = *(uint32_t*)&h2;
                }
            }

    const uint32_t as_base = (uint32_t)__cvta_generic_to_shared(As);
    // ldmatrix per-lane row offset (bytes): lanes 0-15 rows 0-15 k-lo,
    // lanes 16-31 rows 0-15 k-hi(+8 halves).
    const uint32_t rowoff_b = 2u * ((uint32_t)(lane & 15) * ASTRH + (uint32_t)(lane >> 4) * 8);

    auto load_chunk = [&](int c) {
        const int k0 = c * 256;
        __half* dst = As + (size_t)(c & 1) * 64 * ASTRH;
#pragma unroll
        for (int rep = 0; rep < 8; rep++) {
            const int idx = rep * 256 + tid;
            const int b = idx >> 5, q = idx & 31;
            cp16cg(&dst[b * ASTRH + q * 8], &g_h[(size_t)b * HID + k0 + q * 8]);
        }
        cp_commit();
    };

    unsigned phase = 0;

    for (int t = 0; t < TT; t++) {
        // prefetch epilogue operands (g_xg DRAM; g_h own-written last step)
        const size_t SL = (size_t)TT * BATCH * HID;
        const size_t xo0 = (size_t)t * BATCH * HID + (size_t)m0 * HID + hcol;
        const size_t xo1 = xo0 + (size_t)32 * HID;
        const float xr0 = __ldg(&g_xg[xo0]);
        const float xz0 = __ldg(&g_xg[SL + xo0]);
        const float xn0 = __ldg(&g_xg[2 * SL + xo0]);
        const float xr1 = __ldg(&g_xg[xo1]);
        const float xz1 = __ldg(&g_xg[SL + xo1]);
        const float xn1 = __ldg(&g_xg[2 * SL + xo1]);
        const float hv0 = __half2float(g_h[(size_t)m0 * HID + hcol]);
        const float hv1 = __half2float(g_h[(size_t)(m0 + 32) * HID + hcol]);

        // ---------------- Phase A: D = h @ W^T ----------------
        float acc[4][3][4];
#pragma unroll
        for (int mt = 0; mt < 4; mt++)
#pragma unroll
            for (int nt = 0; nt < 3; nt++)
#pragma unroll
                for (int q = 0; q < 4; q++) acc[mt][nt][q] = 0.0f;

        load_chunk(0);
#pragma unroll
        for (int c = 0; c < 4; c++) {
            if (c < 3) {
                load_chunk(c + 1);
                asm volatile("cp.async.wait_group 1;\n");
            } else {
                asm volatile("cp.async.wait_group 0;\n");
            }
            __syncthreads();

            const uint32_t buf = as_base + (uint32_t)(c & 1) * ABUF_B;
#pragma unroll
            for (int s2 = 0; s2 < 2; s2++) {
                const uint32_t kb_b = 2u * (uint32_t)(w * 32 + s2 * 16);
#pragma unroll
                for (int mt = 0; mt < 4; mt++) {
                    uint32_t a0, a1, a2, a3;
                    const uint32_t addr = buf + 2u * (uint32_t)(mt * 16 * ASTRH)
                                        + kb_b + rowoff_b;
                    ldsm_x4(a0, a1, a2, a3, addr);
#pragma unroll
                    for (int nt = 0; nt < 3; nt++)
                        mma_f16(acc[mt][nt], a0, a1, a2, a3,
                                wreg[c][s2][nt][0], wreg[c][s2][nt][1]);
                }
            }
            __syncthreads();
        }

        // ---------------- k-reduction across all 8 warps ----------------
#pragma unroll
        for (int mt = 0; mt < 4; mt++)
#pragma unroll
            for (int nt = 0; nt < 3; nt++) {
                const int tile = mt * 3 + nt;
                *(float4*)&red[((w * 12 + tile) * 128) + lane * 4] =
                    make_float4(acc[mt][nt][0], acc[mt][nt][1],
                                acc[mt][nt][2], acc[mt][nt][3]);
            }
        __syncthreads();

#pragma unroll
        for (int j = 0; j < 6; j++) {
            const int o    = tid + j * 256;      // 0..1535
            const int tile = o >> 7;
            const int rem  = o & 127;
            float ssum = 0.0f;
#pragma unroll
            for (int w2 = 0; w2 < 8; w2++)
                ssum += red[((w2 * 12 + tile) * 128) + rem];
            const int mt = tile / 3;
            const int nt = tile - mt * 3;
            const int la = rem >> 2;
            const int qq = rem & 3;
            const int m  = mt * 16 + (la >> 2) + (qq >> 1) * 8;          // batch
            const int n  = nt * 8 + (la & 3) * 2 + (qq & 1);             // gate*8+col
            pre[n * PRE_STR + m] = ssum;
        }
        __syncthreads();

        // ---------------- fused gate epilogue (own 8 cols) ----------------
        {
            const float Ar0 = pre[ec * PRE_STR + m0];
            const float Az0 = pre[(8 + ec) * PRE_STR + m0];
            const float An0 = pre[(16 + ec) * PRE_STR + m0];
            const float r0 = sigmoidf_fast(xr0 + Ar0 + bR);
            const float z0 = sigmoidf_fast(xz0 + Az0 + bZ);
            const float n0 = tanhf_fast(xn0 + r0 * (An0 + bN));
            const float h0 = (1.0f - z0) * n0 + z0 * hv0;
            g_h[(size_t)m0 * HID + hcol] = __float2half(h0);
            out[((size_t)m0 * TT + t) * HID + hcol] = h0;

            const int m1 = m0 + 32;
            const float Ar1 = pre[ec * PRE_STR + m1];
            const float Az1 = pre[(8 + ec) * PRE_STR + m1];
            const float An1 = pre[(16 + ec) * PRE_STR + m1];
            const float r1 = sigmoidf_fast(xr1 + Ar1 + bR);
            const float z1 = sigmoidf_fast(xz1 + Az1 + bZ);
            const float n1 = tanhf_fast(xn1 + r1 * (An1 + bN));
            const float h1 = (1.0f - z1) * n1 + z1 * hv1;
            g_h[(size_t)m1 * HID + hcol] = __float2half(h1);
            out[((size_t)m1 * TT + t) * HID + hcol] = h1;
        }

        grid_barrier(phase);
    }
}

// ---------------------------------------------------------------------------
extern "C" void kernel_launch(void* const* d_in, const int* in_sizes, int n_in,
                              void* d_out, int out_size)
{
    const float* x     = (const float*)d_in[0];
    const float* W_i_r = (const float*)d_in[1];
    const float* b_i_r = (const float*)d_in[2];
    const float* W_h_r = (const float*)d_in[3];
    const float* b_h_r = (const float*)d_in[4];
    const float* W_i_z = (const float*)d_in[5];
    const float* b_i_z = (const float*)d_in[6];
    const float* W_h_z = (const float*)d_in[7];
    const float* b_h_z = (const float*)d_in[8];
    const float* W_i_n = (const float*)d_in[9];
    const float* b_i_n = (const float*)d_in[10];
    const float* W_h_n = (const float*)d_in[11];
    const float* b_h_n = (const float*)d_in[12];
    float* out = (float*)d_out;

    cudaFuncSetAttribute(recur_kernel, cudaFuncAttributeMaxDynamicSharedMemorySize,
                         RSMEM_BYTES);

    reset_kernel<<<(BATCH * HID + 255) / 256, 256>>>();

    dim3 ig(HID / 64, (BATCH * TT) / 128, 3);
    igemm_tf32_kernel<<<ig, 256>>>(x, W_i_r, W_i_z, W_i_n, b_i_r, b_i_z, b_i_n);

    recur_kernel<<<RGRID, NTHR, RSMEM_BYTES>>>(W_h_r, W_h_z, W_h_n,
                                               b_h_r, b_h_z, b_h_n, out);
}